// round 1
// baseline (speedup 1.0000x reference)
#include <cuda_runtime.h>
#include <cuda_bf16.h>

// Problem constants (B=8, N=2048, F_in=256, H=4, D=64):
//   out[b,n,c] = a * (h[b,n,:] @ W2[:,c]) + (1-a) * h[b,n,c]
// where W2[f, head*64+d] = W[head, f, d], a = clip(res_alpha, 0, 1).
// The attention block in the reference is an exact identity:
// sum_j softmax(e)[i,j] == 1, so out = hp (row-wise scale of 1).
// adj is unused.

#define K_DIM 256
#define BM 128
#define BN 128
#define BK 16
#define TM 8
#define TN 8
#define NTHREADS 256

__global__ __launch_bounds__(NTHREADS, 2)
void gat_fused_gemm_kernel(const float* __restrict__ h,
                           const float* __restrict__ W,        // [4, 256, 64]
                           const float* __restrict__ res_alpha,
                           float* __restrict__ out,
                           int M)
{
    __shared__ float As[BK][BM];      // A stored transposed: As[k][m]
    __shared__ float Bs[BK][BN];      // Bs[k][n]

    const int tid = threadIdx.x;
    const int m0 = blockIdx.y * BM;
    const int n0 = blockIdx.x * BN;

    // 16 x 16 thread grid, each thread owns an 8x8 (TM x TN) register tile.
    const int tx = tid & 15;          // n direction
    const int ty = tid >> 4;          // m direction
    const int tm0 = ty * TM;
    const int tn0 = tx * TN;

    float acc[TM][TN];
    #pragma unroll
    for (int i = 0; i < TM; ++i)
        #pragma unroll
        for (int j = 0; j < TN; ++j)
            acc[i][j] = 0.0f;

    for (int k0 = 0; k0 < K_DIM; k0 += BK) {
        // ---- Load A tile: BM x BK (row-major, k contiguous). 512 float4s.
        #pragma unroll
        for (int i = 0; i < 2; ++i) {
            int v = tid + i * NTHREADS;
            int row = v >> 2;                // v / (BK/4)
            int col = (v & 3) << 2;
            float4 a4 = *reinterpret_cast<const float4*>(
                &h[(size_t)(m0 + row) * K_DIM + k0 + col]);
            As[col + 0][row] = a4.x;
            As[col + 1][row] = a4.y;
            As[col + 2][row] = a4.z;
            As[col + 3][row] = a4.w;
        }
        // ---- Load B tile: BK x BN. B[k][n] = W[head][k0+k][d], head=n>>6, d=n&63.
        #pragma unroll
        for (int i = 0; i < 2; ++i) {
            int v = tid + i * NTHREADS;
            int k = v >> 5;                  // v / (BN/4)
            int n4 = (v & 31) << 2;          // n offset in tile, mult of 4
            int n = n0 + n4;
            int head = n >> 6;
            int d = n & 63;
            float4 b4 = *reinterpret_cast<const float4*>(
                &W[((size_t)head * K_DIM + (k0 + k)) * 64 + d]);
            *reinterpret_cast<float4*>(&Bs[k][n4]) = b4;
        }
        __syncthreads();

        // ---- Compute
        #pragma unroll
        for (int kk = 0; kk < BK; ++kk) {
            float ar[TM], br[TN];
            #pragma unroll
            for (int i = 0; i < TM; ++i) ar[i] = As[kk][tm0 + i];
            #pragma unroll
            for (int j = 0; j < TN; ++j) br[j] = Bs[kk][tn0 + j];
            #pragma unroll
            for (int i = 0; i < TM; ++i)
                #pragma unroll
                for (int j = 0; j < TN; ++j)
                    acc[i][j] = fmaf(ar[i], br[j], acc[i][j]);
        }
        __syncthreads();
    }

    // ---- Fused residual epilogue: out = a*acc + (1-a)*h
    float a = res_alpha[0];
    a = fminf(fmaxf(a, 0.0f), 1.0f);
    const float ra = 1.0f - a;

    #pragma unroll
    for (int i = 0; i < TM; ++i) {
        const int row = m0 + tm0 + i;
        #pragma unroll
        for (int j = 0; j < TN; j += 4) {
            const int col = n0 + tn0 + j;
            float4 hv = *reinterpret_cast<const float4*>(
                &h[(size_t)row * K_DIM + col]);
            float4 o;
            o.x = fmaf(a, acc[i][j + 0], ra * hv.x);
            o.y = fmaf(a, acc[i][j + 1], ra * hv.y);
            o.z = fmaf(a, acc[i][j + 2], ra * hv.z);
            o.w = fmaf(a, acc[i][j + 3], ra * hv.w);
            *reinterpret_cast<float4*>(&out[(size_t)row * K_DIM + col]) = o;
        }
    }
}

extern "C" void kernel_launch(void* const* d_in, const int* in_sizes, int n_in,
                              void* d_out, int out_size) {
    const float* h         = (const float*)d_in[0];   // [B, N, 256]
    // d_in[1] = adj (unused)
    const float* W         = (const float*)d_in[2];   // [4, 256, 64]
    const float* res_alpha = (const float*)d_in[3];   // scalar
    float* out             = (float*)d_out;

    const int M = in_sizes[0] / K_DIM;                // B*N = 16384

    dim3 grid(256 / BN, M / BM);                      // (2, 128)
    dim3 block(NTHREADS);
    gat_fused_gemm_kernel<<<grid, block>>>(h, W, res_alpha, out, M);
}

// round 3
// speedup vs baseline: 1.3654x; 1.3654x over previous
#include <cuda_runtime.h>
#include <cstdint>

// out[m,n] = a * (h[m,:] @ B2[:,n]) + (1-a) * h[m,n]
// B2[k, head*64+d] = W[head,k,d]; a = clip(res_alpha,0,1).
// (softmax row-sums are exactly 1 -> attention block is identity; adj unused)
//
// GEMM M=16384, N=256, K=256 via mma.sync.m16n8k8 tf32 (sm_80 baseline PTX,
// runs on sm_103 HMMA fallback; tcgen05 is rejected by this harness's
// plain-sm_103 PTX target).  3xTF32 split for fp32 accuracy:
//   x = hi + lo, hi = x & 0xFFFFE000 (exactly tf32-representable)
//   D = Ahi*Bhi + Ahi*Blo + Alo*Bhi    (lo*lo ~2^-26, dropped)

#define K_DIM   256
#define NDIM    256
#define BM      128
#define BN      128
#define KC      32
#define LDS_    36            // smem row stride in floats (pad for frag loads)
#define THREADS 256
#define HIMASK  0xFFFFE000u

__device__ float g_Bt[NDIM * K_DIM];   // W transposed: [n][k]

// ---- prep: g_Bt[n][k] = W[head][k][d], n = head*64+d ----
__global__ void prep_Bt(const float* __restrict__ W) {
    int idx = blockIdx.x * blockDim.x + threadIdx.x;   // 65536
    int k = idx >> 8;
    int n = idx & 255;
    int head = n >> 6, d = n & 63;
    g_Bt[n * K_DIM + k] = W[((size_t)head * K_DIM + k) * 64 + d];
}

__device__ __forceinline__ void mma_tf32(float d[4],
                                         uint32_t a0, uint32_t a1, uint32_t a2, uint32_t a3,
                                         uint32_t b0, uint32_t b1) {
    asm volatile(
        "mma.sync.aligned.m16n8k8.row.col.f32.tf32.tf32.f32 "
        "{%0,%1,%2,%3}, {%4,%5,%6,%7}, {%8,%9}, {%0,%1,%2,%3};"
        : "+f"(d[0]), "+f"(d[1]), "+f"(d[2]), "+f"(d[3])
        : "r"(a0), "r"(a1), "r"(a2), "r"(a3), "r"(b0), "r"(b1));
}

__global__ __launch_bounds__(THREADS, 2)
void gat_mma_gemm(const float* __restrict__ h,
                  const float* __restrict__ res_alpha,
                  float* __restrict__ out)
{
    __shared__ float As[BM * LDS_];    // [row][k], stride 36
    __shared__ float Bs[BN * LDS_];    // [n][k],  stride 36

    const int tid = threadIdx.x;
    const int wid = tid >> 5;
    const int lid = tid & 31;
    const int grp = lid >> 2;          // 0..7
    const int tig = lid & 3;           // 0..3

    const int m0 = blockIdx.y * BM;
    const int n0 = blockIdx.x * BN;
    const int wm = (wid & 3) * 32;     // warp M offset in tile
    const int wn = (wid >> 2) * 64;    // warp N offset in tile

    // acc[mt][nt][4]: warp tile 32x64 = 2 Mtiles x 8 Ntiles of 16x8
    float acc[2][8][4];
    #pragma unroll
    for (int mt = 0; mt < 2; ++mt)
        #pragma unroll
        for (int nt = 0; nt < 8; ++nt)
            #pragma unroll
            for (int q = 0; q < 4; ++q)
                acc[mt][nt][q] = 0.0f;

    for (int k0 = 0; k0 < K_DIM; k0 += KC) {
        // ---- cooperative loads: 1024 float4 per tile, 4 per thread ----
        #pragma unroll
        for (int j = 0; j < 4; ++j) {
            int fid = tid + j * THREADS;          // 0..1023
            int row = fid >> 3;
            int kq = (fid & 7) << 2;
            float4 av = *reinterpret_cast<const float4*>(
                &h[(size_t)(m0 + row) * K_DIM + k0 + kq]);
            *reinterpret_cast<float4*>(&As[row * LDS_ + kq]) = av;
            float4 bv = *reinterpret_cast<const float4*>(
                &g_Bt[(size_t)(n0 + row) * K_DIM + k0 + kq]);
            *reinterpret_cast<float4*>(&Bs[row * LDS_ + kq]) = bv;
        }
        __syncthreads();

        #pragma unroll
        for (int k8 = 0; k8 < KC / 8; ++k8) {
            const int kb = k8 * 8;

            // A fragments (both M tiles), split hi/lo in registers
            uint32_t ah[2][4], al[2][4];
            #pragma unroll
            for (int mt = 0; mt < 2; ++mt) {
                const int abase = (wm + mt * 16 + grp) * LDS_ + kb + tig;
                float f0 = As[abase];
                float f1 = As[abase + 8 * LDS_];
                float f2 = As[abase + 4];
                float f3 = As[abase + 8 * LDS_ + 4];
                ah[mt][0] = __float_as_uint(f0) & HIMASK;
                ah[mt][1] = __float_as_uint(f1) & HIMASK;
                ah[mt][2] = __float_as_uint(f2) & HIMASK;
                ah[mt][3] = __float_as_uint(f3) & HIMASK;
                al[mt][0] = __float_as_uint(f0 - __uint_as_float(ah[mt][0]));
                al[mt][1] = __float_as_uint(f1 - __uint_as_float(ah[mt][1]));
                al[mt][2] = __float_as_uint(f2 - __uint_as_float(ah[mt][2]));
                al[mt][3] = __float_as_uint(f3 - __uint_as_float(ah[mt][3]));
            }

            #pragma unroll
            for (int nt = 0; nt < 8; ++nt) {
                const int bbase = (wn + nt * 8 + grp) * LDS_ + kb + tig;
                float g0 = Bs[bbase];
                float g1 = Bs[bbase + 4];
                uint32_t bh0 = __float_as_uint(g0) & HIMASK;
                uint32_t bh1 = __float_as_uint(g1) & HIMASK;
                uint32_t bl0 = __float_as_uint(g0 - __uint_as_float(bh0));
                uint32_t bl1 = __float_as_uint(g1 - __uint_as_float(bh1));

                #pragma unroll
                for (int mt = 0; mt < 2; ++mt) {
                    mma_tf32(acc[mt][nt], ah[mt][0], ah[mt][1], ah[mt][2], ah[mt][3], bh0, bh1);
                    mma_tf32(acc[mt][nt], ah[mt][0], ah[mt][1], ah[mt][2], ah[mt][3], bl0, bl1);
                    mma_tf32(acc[mt][nt], al[mt][0], al[mt][1], al[mt][2], al[mt][3], bh0, bh1);
                }
            }
        }
        __syncthreads();
    }

    // ---- epilogue: out = a*acc + (1-a)*h, float2 per (c0,c1)/(c2,c3) pair ----
    float a = res_alpha[0];
    a = fminf(fmaxf(a, 0.0f), 1.0f);
    const float ra = 1.0f - a;

    #pragma unroll
    for (int mt = 0; mt < 2; ++mt) {
        const int r0 = m0 + wm + mt * 16 + grp;
        #pragma unroll
        for (int nt = 0; nt < 8; ++nt) {
            const int c = n0 + wn + nt * 8 + 2 * tig;
            {
                size_t gi = (size_t)r0 * NDIM + c;
                float2 hv = *reinterpret_cast<const float2*>(&h[gi]);
                float2 o;
                o.x = fmaf(a, acc[mt][nt][0], ra * hv.x);
                o.y = fmaf(a, acc[mt][nt][1], ra * hv.y);
                *reinterpret_cast<float2*>(&out[gi]) = o;
            }
            {
                size_t gi = (size_t)(r0 + 8) * NDIM + c;
                float2 hv = *reinterpret_cast<const float2*>(&h[gi]);
                float2 o;
                o.x = fmaf(a, acc[mt][nt][2], ra * hv.x);
                o.y = fmaf(a, acc[mt][nt][3], ra * hv.y);
                *reinterpret_cast<float2*>(&out[gi]) = o;
            }
        }
    }
}

extern "C" void kernel_launch(void* const* d_in, const int* in_sizes, int n_in,
                              void* d_out, int out_size) {
    const float* h         = (const float*)d_in[0];   // [8, 2048, 256]
    // d_in[1] = adj (unused)
    const float* W         = (const float*)d_in[2];   // [4, 256, 64]
    const float* res_alpha = (const float*)d_in[3];
    float* out             = (float*)d_out;

    const int M = in_sizes[0] / K_DIM;                // 16384

    prep_Bt<<<(NDIM * K_DIM) / 256, 256>>>(W);

    dim3 grid(NDIM / BN, M / BM);                     // (2, 128)
    gat_mma_gemm<<<grid, THREADS>>>(h, res_alpha, out);
}